// round 8
// baseline (speedup 1.0000x reference)
#include <cuda_runtime.h>
#include <cstdint>

#define LN_EPS 1e-5f
#define H 768
#define F 11
#define RPB 64            // rows per block
#define TPB 96            // 96 threads x 8 cols = 768
#define CHUNK 8           // rows per bulk-store chunk (24KB)
#define NCHUNK (RPB / CHUNK)
#define ROWBYTES (H * 4)  // 3072

// [0..120] G[i*11+j], [121..131] ws, [132..142] Wb, [143] sum_b, [144] sum_b2
__device__ float g_stats[145];

typedef unsigned long long ull;

__device__ __forceinline__ ull fma2(ull a, ull b, ull c) {
    ull d; asm("fma.rn.f32x2 %0, %1, %2, %3;" : "=l"(d) : "l"(a), "l"(b), "l"(c)); return d;
}
__device__ __forceinline__ void unpk(ull v, float& lo, float& hi) {
    asm("mov.b64 {%0, %1}, %2;" : "=f"(lo), "=f"(hi) : "l"(v));
}
__device__ __forceinline__ ull pk2(float lo, float hi) {
    ull d; asm("mov.b64 %0, {%1, %2};" : "=l"(d) : "f"(lo), "f"(hi)); return d;
}
__device__ __forceinline__ uint32_t smem_u32(const void* p) {
    uint32_t a;
    asm("{ .reg .u64 t; cvta.to.shared.u64 t, %1; cvt.u32.u64 %0, t; }" : "=r"(a) : "l"(p));
    return a;
}

// ---------------------------------------------------------------------------
// Kernel A: weight statistics — single block, W+b staged in smem,
// 145 warp-reduced tasks over 24 warps.
// ---------------------------------------------------------------------------
__global__ void __launch_bounds__(768)
stats_kernel(const float* __restrict__ W, const float* __restrict__ b) {
    __shared__ float sW[F][H];   // 33KB
    __shared__ float sb[H];
    int tid = threadIdx.x;
    for (int i = tid; i < F * H; i += 768) sW[i / H][i % H] = W[i];
    sb[tid] = b[tid];
    __syncthreads();

    int wid = tid >> 5, lane = tid & 31;
    for (int task = wid; task < 145; task += 24) {
        float local = 0.f;
        if (task < 121) {
            int i = task / 11, j = task % 11;
            for (int h = lane; h < H; h += 32) local += sW[i][h] * sW[j][h];
        } else if (task < 132) {
            int f = task - 121;
            for (int h = lane; h < H; h += 32) local += sW[f][h];
        } else if (task < 143) {
            int f = task - 132;
            for (int h = lane; h < H; h += 32) local += sW[f][h] * sb[h];
        } else if (task == 143) {
            for (int h = lane; h < H; h += 32) local += sb[h];
        } else {
            for (int h = lane; h < H; h += 32) local += sb[h] * sb[h];
        }
        #pragma unroll
        for (int o = 16; o; o >>= 1) local += __shfl_xor_sync(0xffffffffu, local, o);
        if (lane == 0) g_stats[task] = local;
    }
}

// ---------------------------------------------------------------------------
// Kernel B (fused): feats -> smem duplicated pairs, packed-FFMA2
// GEMV+LN+ReLU into double-buffered smem tiles, TMA bulk stores.
// ---------------------------------------------------------------------------
__global__ void __launch_bounds__(TPB, 4)
fused_kernel(const float* __restrict__ target, const float* __restrict__ boxes,
             const float* __restrict__ W, const float* __restrict__ b,
             const float* __restrict__ gamma, const float* __restrict__ beta,
             float* __restrict__ out, int N) {
    __shared__ __align__(128) float obuf[2][CHUNK * H];   // 2 x 24KB
    __shared__ __align__(16)  float fst[RPB][32];         // 13 duplicated pairs + pad
    __shared__ float st[148];

    int tid = threadIdx.x;
    int h0 = tid * 8;

    for (int i = tid; i < 145; i += TPB) st[i] = g_stats[i];

    // resident slices (packed pairs): wg = W*gamma, bg = b*gamma, gp, ep
    ull gp[4], ep[4], bg[4];
    float g8[8];
    {
        float4 ga = *(const float4*)(gamma + h0);
        float4 gb = *(const float4*)(gamma + h0 + 4);
        float4 ea = *(const float4*)(beta + h0);
        float4 eb = *(const float4*)(beta + h0 + 4);
        float4 ba = *(const float4*)(b + h0);
        float4 bb = *(const float4*)(b + h0 + 4);
        g8[0]=ga.x; g8[1]=ga.y; g8[2]=ga.z; g8[3]=ga.w;
        g8[4]=gb.x; g8[5]=gb.y; g8[6]=gb.z; g8[7]=gb.w;
        gp[0] = pk2(ga.x, ga.y); gp[1] = pk2(ga.z, ga.w);
        gp[2] = pk2(gb.x, gb.y); gp[3] = pk2(gb.z, gb.w);
        ep[0] = pk2(ea.x, ea.y); ep[1] = pk2(ea.z, ea.w);
        ep[2] = pk2(eb.x, eb.y); ep[3] = pk2(eb.z, eb.w);
        bg[0] = pk2(ba.x * g8[0], ba.y * g8[1]);
        bg[1] = pk2(ba.z * g8[2], ba.w * g8[3]);
        bg[2] = pk2(bb.x * g8[4], bb.y * g8[5]);
        bg[3] = pk2(bb.z * g8[6], bb.w * g8[7]);
    }
    ull wg[F][4];
    #pragma unroll
    for (int f = 0; f < F; f++) {
        float4 wa = *(const float4*)(W + f * H + h0);
        float4 wb = *(const float4*)(W + f * H + h0 + 4);
        wg[f][0] = pk2(wa.x * g8[0], wa.y * g8[1]);
        wg[f][1] = pk2(wa.z * g8[2], wa.w * g8[3]);
        wg[f][2] = pk2(wb.x * g8[4], wb.y * g8[5]);
        wg[f][3] = pk2(wb.z * g8[6], wb.w * g8[7]);
    }

    int r0blk = blockIdx.x * RPB;
    __syncthreads();   // st[] ready

    // ---- feats phase: one row per thread (tid < 64) ----
    if (tid < RPB) {
        int row = r0blk + tid;
        if (row < N) {
            float tx0 = target[0], ty0 = target[1], tx1 = target[2], ty1 = target[3];
            float4 bx = ((const float4*)boxes)[row];
            float x0 = bx.x, y0 = bx.y, x1 = bx.z, y1 = bx.w;

            float w1 = tx1 - tx0, h1 = ty1 - ty0;
            float w2 = x1 - x0,   h2 = y1 - y0;

            float t[F];
            t[0] = w1; t[1] = h1; t[2] = w2; t[3] = h2;
            t[4] = fabsf(w1 - w2); t[5] = fabsf(h1 - h2);

            float c1x = (tx0 + tx1) * 0.5f, c1y = (ty0 + ty1) * 0.5f;
            float c2x = (x0 + x1) * 0.5f,   c2y = (y0 + y1) * 0.5f;
            float dx = c2x - c1x, dy = c2y - c1y;
            t[6] = sqrtf(dx * dx + dy * dy);

            bool overlap = (tx0 < x1) && (tx1 > x0) && (ty0 < y1) && (ty1 > y0);
            float xi0 = fmaxf(tx0, x0), yi0 = fmaxf(ty0, y0);
            float xi1 = fminf(tx1, x1), yi1 = fminf(ty1, y1);
            float inter = overlap ? (xi1 - xi0) * (yi1 - yi0) : 0.f;
            float a1 = w1 * h1, a2 = w2 * h2;
            float uni = a1 + a2 - inter;
            t[7] = inter / uni; t[8] = inter / a1; t[9] = inter / a2;

            float degree = atan2f(fabsf(dy), fabsf(dx)) * 57.29577951308232f;
            float bucket;
            if      (degree >  22.5f && degree <=  67.5f) bucket = 1.f;
            else if (degree >  67.5f && degree <= 112.5f) bucket = 2.f;
            else if (degree > 112.5f && degree <= 157.5f) bucket = 3.f;
            else if (degree > 157.5f && degree <= 202.5f) bucket = 4.f;
            else if (degree > 202.5f && degree <= 247.5f) bucket = 5.f;
            else if (degree > 247.5f && degree <= 292.5f) bucket = 6.f;
            else if (degree > 292.5f && degree <= 337.5f) bucket = 7.f;
            else bucket = 8.f;
            t[10] = bucket;

            // closed-form LN stats: S1 = t.ws + sum_b ; S2 = t'Gt + 2 t.Wb + sum_b2
            const float* G  = st;
            const float* ws = st + 121;
            const float* Wb = st + 132;
            float S1 = st[143];
            float S2 = st[144];
            #pragma unroll
            for (int i = 0; i < F; i++) {
                S1 += t[i] * ws[i];
                S2 += 2.f * t[i] * Wb[i];
                float gi = 0.f;
                #pragma unroll
                for (int j = 0; j < F; j++) gi += G[i * 11 + j] * t[j];
                S2 += t[i] * gi;
            }
            float mean = S1 * (1.f / (float)H);
            float var  = S2 * (1.f / (float)H) - mean * mean;
            float inv  = rsqrtf(var + LN_EPS);

            float2* fp = (float2*)fst[tid];
            #pragma unroll
            for (int i = 0; i < F; i++) {
                float u = t[i] * inv;
                fp[i] = make_float2(u, u);
            }
            fp[11] = make_float2(inv, inv);
            float p = -mean * inv;
            fp[12] = make_float2(p, p);
            fp[13] = make_float2(0.f, 0.f);
        }
    }
    __syncthreads();

    // ---- chunk loop: compute into smem, bulk-store to global ----
    for (int c = 0; c < NCHUNK; ++c) {
        int cr0 = r0blk + c * CHUNK;
        if (cr0 >= N) break;
        int nrows = min(CHUNK, N - cr0);
        float* buf = obuf[c & 1];

        if (c >= 2) {
            if (tid == 0)
                asm volatile("cp.async.bulk.wait_group 1;" ::: "memory");
            __syncthreads();
        }

        for (int i = 0; i < nrows; ++i) {
            const ulonglong2* fq = (const ulonglong2*)fst[c * CHUNK + i];
            ulonglong2 q0 = fq[0], q1 = fq[1], q2 = fq[2], q3 = fq[3];
            ulonglong2 q4 = fq[4], q5 = fq[5], q6 = fq[6];
            ull u[F] = {q0.x, q0.y, q1.x, q1.y, q2.x, q2.y,
                        q3.x, q3.y, q4.x, q4.y, q5.x};
            ull s2 = q5.y;   // (inv, inv)
            ull p2 = q6.x;   // (-mean*inv, ..)

            ull acc[4];
            #pragma unroll
            for (int k = 0; k < 4; k++) acc[k] = fma2(p2, gp[k], ep[k]);
            #pragma unroll
            for (int k = 0; k < 4; k++) acc[k] = fma2(s2, bg[k], acc[k]);
            #pragma unroll
            for (int f = 0; f < F; f++) {
                #pragma unroll
                for (int k = 0; k < 4; k++) acc[k] = fma2(u[f], wg[f][k], acc[k]);
            }

            float v0, v1, v2, v3, v4, v5, v6, v7;
            unpk(acc[0], v0, v1); unpk(acc[1], v2, v3);
            unpk(acc[2], v4, v5); unpk(acc[3], v6, v7);
            float4 o0, o1;
            o0.x = fmaxf(v0, 0.f); o0.y = fmaxf(v1, 0.f);
            o0.z = fmaxf(v2, 0.f); o0.w = fmaxf(v3, 0.f);
            o1.x = fmaxf(v4, 0.f); o1.y = fmaxf(v5, 0.f);
            o1.z = fmaxf(v6, 0.f); o1.w = fmaxf(v7, 0.f);

            float4* op = (float4*)(buf + i * H + h0);
            op[0] = o0; op[1] = o1;
        }

        asm volatile("fence.proxy.async.shared::cta;" ::: "memory");
        __syncthreads();

        if (tid == 0) {
            uint32_t saddr = smem_u32(buf);
            const void* gptr = (const void*)(out + (size_t)cr0 * H);
            uint32_t bytes = (uint32_t)nrows * ROWBYTES;
            asm volatile(
                "cp.async.bulk.global.shared::cta.bulk_group [%0], [%1], %2;"
                :: "l"(gptr), "r"(saddr), "r"(bytes) : "memory");
            asm volatile("cp.async.bulk.commit_group;" ::: "memory");
        }
    }

    if (tid == 0)
        asm volatile("cp.async.bulk.wait_group 0;" ::: "memory");
}

// ---------------------------------------------------------------------------
extern "C" void kernel_launch(void* const* d_in, const int* in_sizes, int n_in,
                              void* d_out, int out_size) {
    if (n_in < 6) return;
    const float* target = (const float*)d_in[0];
    const float* boxes  = (const float*)d_in[1];
    const float* W      = (const float*)d_in[2];
    const float* b      = (const float*)d_in[3];
    const float* gamma  = (const float*)d_in[4];
    const float* beta   = (const float*)d_in[5];
    float* out = (float*)d_out;

    int N = in_sizes[1] / 4;

    stats_kernel<<<1, 768>>>(W, b);
    fused_kernel<<<(N + RPB - 1) / RPB, TPB>>>(target, boxes, W, b, gamma, beta, out, N);
}

// round 10
// speedup vs baseline: 1.1847x; 1.1847x over previous
#include <cuda_runtime.h>
#include <cstdint>

#define LN_EPS 1e-5f
#define H 768
#define F 11
#define RPB 64            // rows per block
#define TPB 96            // 96 threads x 8 cols = 768
#define CHUNK 8           // rows per bulk-store chunk (24KB)
#define NCHUNK (RPB / CHUNK)
#define ROWBYTES (H * 4)  // 3072
#define FSTRIDE 28        // floats per fst row (13 dup pairs + 2 pad), 112B (16B-aligned)

// [0..120] G[i*11+j], [121..131] ws, [132..142] Wb, [143] sum_b, [144] sum_b2
__device__ float g_stats[145];

typedef unsigned long long ull;

__device__ __forceinline__ ull fma2(ull a, ull b, ull c) {
    ull d; asm("fma.rn.f32x2 %0, %1, %2, %3;" : "=l"(d) : "l"(a), "l"(b), "l"(c)); return d;
}
__device__ __forceinline__ void unpk(ull v, float& lo, float& hi) {
    asm("mov.b64 {%0, %1}, %2;" : "=f"(lo), "=f"(hi) : "l"(v));
}
__device__ __forceinline__ ull pk2(float lo, float hi) {
    ull d; asm("mov.b64 %0, {%1, %2};" : "=l"(d) : "f"(lo), "f"(hi)); return d;
}
__device__ __forceinline__ uint32_t smem_u32(const void* p) {
    uint32_t a;
    asm("{ .reg .u64 t; cvta.to.shared.u64 t, %1; cvt.u32.u64 %0, t; }" : "=r"(a) : "l"(p));
    return a;
}

// ---------------------------------------------------------------------------
// Kernel A: weight statistics (145 tiny reductions over H=768) — R6 version
// ---------------------------------------------------------------------------
__global__ void stats_kernel(const float* __restrict__ W, const float* __restrict__ b) {
    __shared__ float wsum[8];
    int blk = blockIdx.x, tid = threadIdx.x;
    float local = 0.f;
    if (blk < 121) {
        int i = blk / 11, j = blk % 11;
        for (int h = tid; h < H; h += 256) local += W[i * H + h] * W[j * H + h];
    } else if (blk < 132) {
        int f = blk - 121;
        for (int h = tid; h < H; h += 256) local += W[f * H + h];
    } else if (blk < 143) {
        int f = blk - 132;
        for (int h = tid; h < H; h += 256) local += W[f * H + h] * b[h];
    } else if (blk == 143) {
        for (int h = tid; h < H; h += 256) local += b[h];
    } else {
        for (int h = tid; h < H; h += 256) local += b[h] * b[h];
    }
    #pragma unroll
    for (int o = 16; o; o >>= 1) local += __shfl_xor_sync(0xffffffffu, local, o);
    if ((tid & 31) == 0) wsum[tid >> 5] = local;
    __syncthreads();
    if (tid == 0) {
        float s = 0.f;
        #pragma unroll
        for (int w = 0; w < 8; w++) s += wsum[w];
        g_stats[blk] = s;
    }
}

// ---------------------------------------------------------------------------
// Row compute core: one row's GEMV+LN+ReLU into smem tile (8 cols/thread)
// ---------------------------------------------------------------------------
struct ColCtx {
    ull gp[4], ep[4], bg[4];
    ull wg[F][4];
};

__device__ __forceinline__ void compute_row(const float* __restrict__ fsrow,
                                            const ColCtx& C, float* __restrict__ dst,
                                            int h0) {
    const ulonglong2* fq = (const ulonglong2*)fsrow;
    ulonglong2 q0 = fq[0], q1 = fq[1], q2 = fq[2];
    ulonglong2 q3 = fq[3], q4 = fq[4], q5 = fq[5];
    ull last = *(const ull*)(fsrow + 24);
    ull u[F] = {q0.x, q0.y, q1.x, q1.y, q2.x, q2.y,
                q3.x, q3.y, q4.x, q4.y, q5.x};
    ull s2 = q5.y;   // (inv, inv)
    ull p2 = last;   // (-mean*inv, -mean*inv)

    ull acc[4];
    #pragma unroll
    for (int k = 0; k < 4; k++) acc[k] = fma2(p2, C.gp[k], C.ep[k]);
    #pragma unroll
    for (int k = 0; k < 4; k++) acc[k] = fma2(s2, C.bg[k], acc[k]);
    #pragma unroll
    for (int f = 0; f < F; f++) {
        #pragma unroll
        for (int k = 0; k < 4; k++) acc[k] = fma2(u[f], C.wg[f][k], acc[k]);
    }

    float v0, v1, v2, v3, v4, v5, v6, v7;
    unpk(acc[0], v0, v1); unpk(acc[1], v2, v3);
    unpk(acc[2], v4, v5); unpk(acc[3], v6, v7);
    float4 o0, o1;
    o0.x = fmaxf(v0, 0.f); o0.y = fmaxf(v1, 0.f);
    o0.z = fmaxf(v2, 0.f); o0.w = fmaxf(v3, 0.f);
    o1.x = fmaxf(v4, 0.f); o1.y = fmaxf(v5, 0.f);
    o1.z = fmaxf(v6, 0.f); o1.w = fmaxf(v7, 0.f);
    float4* op = (float4*)(dst + h0);
    op[0] = o0; op[1] = o1;
}

// ---------------------------------------------------------------------------
// Kernel B (fused): feats -> smem dup pairs, packed-FFMA2 GEMV+LN+ReLU into
// double-buffered smem tiles, TMA bulk stores. Interior blocks take a
// compile-time-unrolled fast path.
// ---------------------------------------------------------------------------
__global__ void __launch_bounds__(TPB, 4)
fused_kernel(const float* __restrict__ target, const float* __restrict__ boxes,
             const float* __restrict__ W, const float* __restrict__ b,
             const float* __restrict__ gamma, const float* __restrict__ beta,
             float* __restrict__ out, int N) {
    __shared__ __align__(128) float obuf[2][CHUNK * H];     // 2 x 24KB
    __shared__ __align__(16)  float fst[RPB][FSTRIDE];      // 7KB
    float* st = obuf[0];   // stats staging aliases tile buffer (pre-loop only)

    int tid = threadIdx.x;
    int h0 = tid * 8;

    for (int i = tid; i < 145; i += TPB) st[i] = g_stats[i];

    // resident slices (packed pairs): wg = W*gamma, bg = b*gamma, gp, ep
    ColCtx C;
    float g8[8];
    {
        float4 ga = *(const float4*)(gamma + h0);
        float4 gb = *(const float4*)(gamma + h0 + 4);
        float4 ea = *(const float4*)(beta + h0);
        float4 eb = *(const float4*)(beta + h0 + 4);
        float4 ba = *(const float4*)(b + h0);
        float4 bb = *(const float4*)(b + h0 + 4);
        g8[0]=ga.x; g8[1]=ga.y; g8[2]=ga.z; g8[3]=ga.w;
        g8[4]=gb.x; g8[5]=gb.y; g8[6]=gb.z; g8[7]=gb.w;
        C.gp[0] = pk2(ga.x, ga.y); C.gp[1] = pk2(ga.z, ga.w);
        C.gp[2] = pk2(gb.x, gb.y); C.gp[3] = pk2(gb.z, gb.w);
        C.ep[0] = pk2(ea.x, ea.y); C.ep[1] = pk2(ea.z, ea.w);
        C.ep[2] = pk2(eb.x, eb.y); C.ep[3] = pk2(eb.z, eb.w);
        C.bg[0] = pk2(ba.x * g8[0], ba.y * g8[1]);
        C.bg[1] = pk2(ba.z * g8[2], ba.w * g8[3]);
        C.bg[2] = pk2(bb.x * g8[4], bb.y * g8[5]);
        C.bg[3] = pk2(bb.z * g8[6], bb.w * g8[7]);
    }
    #pragma unroll
    for (int f = 0; f < F; f++) {
        float4 wa = *(const float4*)(W + f * H + h0);
        float4 wb = *(const float4*)(W + f * H + h0 + 4);
        C.wg[f][0] = pk2(wa.x * g8[0], wa.y * g8[1]);
        C.wg[f][1] = pk2(wa.z * g8[2], wa.w * g8[3]);
        C.wg[f][2] = pk2(wb.x * g8[4], wb.y * g8[5]);
        C.wg[f][3] = pk2(wb.z * g8[6], wb.w * g8[7]);
    }

    int r0blk = blockIdx.x * RPB;
    __syncthreads();   // st[] ready

    // ---- feats phase: one row per thread (tid < 64) ----
    if (tid < RPB) {
        int row = r0blk + tid;
        if (row < N) {
            float tx0 = target[0], ty0 = target[1], tx1 = target[2], ty1 = target[3];
            float4 bx = ((const float4*)boxes)[row];
            float x0 = bx.x, y0 = bx.y, x1 = bx.z, y1 = bx.w;

            float w1 = tx1 - tx0, h1 = ty1 - ty0;
            float w2 = x1 - x0,   h2 = y1 - y0;

            float t[F];
            t[0] = w1; t[1] = h1; t[2] = w2; t[3] = h2;
            t[4] = fabsf(w1 - w2); t[5] = fabsf(h1 - h2);

            float c1x = (tx0 + tx1) * 0.5f, c1y = (ty0 + ty1) * 0.5f;
            float c2x = (x0 + x1) * 0.5f,   c2y = (y0 + y1) * 0.5f;
            float dx = c2x - c1x, dy = c2y - c1y;
            t[6] = sqrtf(dx * dx + dy * dy);

            bool overlap = (tx0 < x1) && (tx1 > x0) && (ty0 < y1) && (ty1 > y0);
            float xi0 = fmaxf(tx0, x0), yi0 = fmaxf(ty0, y0);
            float xi1 = fminf(tx1, x1), yi1 = fminf(ty1, y1);
            float inter = overlap ? (xi1 - xi0) * (yi1 - yi0) : 0.f;
            float a1 = w1 * h1, a2 = w2 * h2;
            float uni = a1 + a2 - inter;
            t[7] = inter / uni; t[8] = inter / a1; t[9] = inter / a2;

            float degree = atan2f(fabsf(dy), fabsf(dx)) * 57.29577951308232f;
            float bucket;
            if      (degree >  22.5f && degree <=  67.5f) bucket = 1.f;
            else if (degree >  67.5f && degree <= 112.5f) bucket = 2.f;
            else if (degree > 112.5f && degree <= 157.5f) bucket = 3.f;
            else if (degree > 157.5f && degree <= 202.5f) bucket = 4.f;
            else if (degree > 202.5f && degree <= 247.5f) bucket = 5.f;
            else if (degree > 247.5f && degree <= 292.5f) bucket = 6.f;
            else if (degree > 292.5f && degree <= 337.5f) bucket = 7.f;
            else bucket = 8.f;
            t[10] = bucket;

            // closed-form LN stats: S1 = t.ws + sum_b ; S2 = t'Gt + 2 t.Wb + sum_b2
            const float* G  = st;
            const float* ws = st + 121;
            const float* Wb = st + 132;
            float S1 = st[143];
            float S2 = st[144];
            #pragma unroll
            for (int i = 0; i < F; i++) {
                S1 += t[i] * ws[i];
                S2 += 2.f * t[i] * Wb[i];
                float gi = 0.f;
                #pragma unroll
                for (int j = 0; j < F; j++) gi += G[i * 11 + j] * t[j];
                S2 += t[i] * gi;
            }
            float mean = S1 * (1.f / (float)H);
            float var  = S2 * (1.f / (float)H) - mean * mean;
            float inv  = rsqrtf(var + LN_EPS);

            float2* fp = (float2*)fst[tid];
            #pragma unroll
            for (int i = 0; i < F; i++) {
                float u = t[i] * inv;
                fp[i] = make_float2(u, u);
            }
            fp[11] = make_float2(inv, inv);
            float p = -mean * inv;
            fp[12] = make_float2(p, p);
        }
    }
    __syncthreads();   // fst ready; st no longer needed (obuf[0] reusable)

    bool interior = (r0blk + RPB <= N);

    // ---- chunk loop: compute into smem, bulk-store to global ----
    #pragma unroll 1
    for (int c = 0; c < NCHUNK; ++c) {
        int cr0 = r0blk + c * CHUNK;
        if (cr0 >= N) break;
        float* buf = obuf[c & 1];

        if (c >= 2) {
            if (tid == 0)
                asm volatile("cp.async.bulk.wait_group 1;" ::: "memory");
            __syncthreads();
        }

        int nrows;
        if (interior) {
            nrows = CHUNK;
            #pragma unroll 2
            for (int i = 0; i < CHUNK; ++i)
                compute_row(fst[c * CHUNK + i], C, buf + i * H, h0);
        } else {
            nrows = min(CHUNK, N - cr0);
            for (int i = 0; i < nrows; ++i)
                compute_row(fst[c * CHUNK + i], C, buf + i * H, h0);
        }

        asm volatile("fence.proxy.async.shared::cta;" ::: "memory");
        __syncthreads();

        if (tid == 0) {
            uint32_t saddr = smem_u32(buf);
            const void* gptr = (const void*)(out + (size_t)cr0 * H);
            uint32_t bytes = (uint32_t)nrows * ROWBYTES;
            asm volatile(
                "cp.async.bulk.global.shared::cta.bulk_group [%0], [%1], %2;"
                :: "l"(gptr), "r"(saddr), "r"(bytes) : "memory");
            asm volatile("cp.async.bulk.commit_group;" ::: "memory");
        }
    }

    if (tid == 0)
        asm volatile("cp.async.bulk.wait_group 0;" ::: "memory");
}

// ---------------------------------------------------------------------------
extern "C" void kernel_launch(void* const* d_in, const int* in_sizes, int n_in,
                              void* d_out, int out_size) {
    if (n_in < 6) return;
    const float* target = (const float*)d_in[0];
    const float* boxes  = (const float*)d_in[1];
    const float* W      = (const float*)d_in[2];
    const float* b      = (const float*)d_in[3];
    const float* gamma  = (const float*)d_in[4];
    const float* beta   = (const float*)d_in[5];
    float* out = (float*)d_out;

    int N = in_sizes[1] / 4;

    stats_kernel<<<145, 256>>>(W, b);
    fused_kernel<<<(N + RPB - 1) / RPB, TPB>>>(target, boxes, W, b, gamma, beta, out, N);
}